// round 5
// baseline (speedup 1.0000x reference)
#include <cuda_runtime.h>
#include <cuda_bf16.h>

#define D 512
#define MAXC 512
#define MAXN 32768

// Scratch (allocation-free rule: __device__ globals)
__device__ int g_counts[MAXC];
__device__ int g_offsets[MAXC + 1];
__device__ int g_cursor[MAXC];
__device__ int g_idx[MAXN];   // row byte-offsets (i*D), grouped by class

// ---------------------------------------------------------------------------
// Pass 0: zero counters + output scalar
__global__ void init_kernel(float* out, int C) {
    int t = blockIdx.x * blockDim.x + threadIdx.x;
    if (t < C) g_counts[t] = 0;
    if (t == 0) out[0] = 0.0f;
}

// ---------------------------------------------------------------------------
// Pass 1: class histogram (smem-staged to keep global atomics tiny)
__global__ void hist_kernel(const int* __restrict__ targets, int N, int C) {
    __shared__ int sh[MAXC];
    for (int i = threadIdx.x; i < C; i += blockDim.x) sh[i] = 0;
    __syncthreads();
    for (int i = blockIdx.x * blockDim.x + threadIdx.x; i < N;
         i += gridDim.x * blockDim.x)
        atomicAdd(&sh[targets[i]], 1);
    __syncthreads();
    for (int i = threadIdx.x; i < C; i += blockDim.x)
        if (sh[i]) atomicAdd(&g_counts[i], sh[i]);
}

// ---------------------------------------------------------------------------
// Pass 2: exclusive scan over <=512 class counts (single block Hillis-Steele)
__global__ void scan_kernel(int C) {
    __shared__ int s[MAXC];
    int t = threadIdx.x;  // blockDim.x == MAXC
    s[t] = (t < C) ? g_counts[t] : 0;
    __syncthreads();
    for (int off = 1; off < MAXC; off <<= 1) {
        int v = s[t];
        int add = (t >= off) ? s[t - off] : 0;
        __syncthreads();
        s[t] = v + add;
        __syncthreads();
    }
    int excl = (t == 0) ? 0 : s[t - 1];
    if (t < C) {
        g_offsets[t] = excl;
        g_cursor[t]  = excl;
    }
    if (t == 0) g_offsets[C] = s[C - 1];
}

// ---------------------------------------------------------------------------
// Pass 3: scatter sample row-offsets into class-grouped index list
__global__ void fill_kernel(const int* __restrict__ targets, int N) {
    for (int i = blockIdx.x * blockDim.x + threadIdx.x; i < N;
         i += gridDim.x * blockDim.x) {
        int c = targets[i];
        int p = atomicAdd(&g_cursor[c], 1);
        g_idx[p] = i * D;  // pre-scaled row offset
    }
}

// ---------------------------------------------------------------------------
// Pass 4: per-(class, modal) gather-reduce + smooth-L1 epilogue.
// gridDim = (C, 2); blockDim = D (one thread per feature dim).
__global__ void reduce_kernel(const float* __restrict__ m1,
                              const float* __restrict__ m2,
                              const float* __restrict__ centers,
                              float* __restrict__ out,
                              float inv_nd) {
    int c = blockIdx.x;
    const float* __restrict__ data = blockIdx.y ? m2 : m1;
    int beg = g_offsets[c];
    int end = g_offsets[c + 1];
    int cnt = end - beg;
    if (cnt == 0) return;  // empty classes contribute 0 (never gathered in ref)

    __shared__ int   sidx[1024];
    __shared__ float swarp[16];

    int d = threadIdx.x;
    float sum = 0.0f;

    for (int cs = beg; cs < end; cs += 1024) {
        int m = min(1024, end - cs);
        __syncthreads();
        for (int j = threadIdx.x; j < m; j += blockDim.x)
            sidx[j] = g_idx[cs + j];
        __syncthreads();

        float s0 = 0.f, s1 = 0.f, s2 = 0.f, s3 = 0.f;
        int j = 0;
        for (; j + 4 <= m; j += 4) {
            s0 += __ldg(data + sidx[j]     + d);
            s1 += __ldg(data + sidx[j + 1] + d);
            s2 += __ldg(data + sidx[j + 2] + d);
            s3 += __ldg(data + sidx[j + 3] + d);
        }
        for (; j < m; j++) s0 += __ldg(data + sidx[j] + d);
        sum += (s0 + s1) + (s2 + s3);
    }

    // Smooth-L1(mean_c,d , centers[c,d]) weighted by class count
    float mean = sum / (float)cnt;
    float ad   = fabsf(mean - __ldg(centers + c * D + d));
    float l    = (ad < 1.0f) ? 0.5f * ad * ad : (ad - 0.5f);
    float v    = l * (float)cnt;

    // Block reduction (512 threads -> 16 warps -> scalar)
    #pragma unroll
    for (int o = 16; o; o >>= 1) v += __shfl_xor_sync(0xffffffff, v, o);
    if ((threadIdx.x & 31) == 0) swarp[threadIdx.x >> 5] = v;
    __syncthreads();
    if (threadIdx.x < 32) {
        float w = (threadIdx.x < (blockDim.x >> 5)) ? swarp[threadIdx.x] : 0.0f;
        #pragma unroll
        for (int o = 8; o; o >>= 1) w += __shfl_xor_sync(0xffffffff, w, o);
        if (threadIdx.x == 0) atomicAdd(out, w * inv_nd);
    }
}

// ---------------------------------------------------------------------------
extern "C" void kernel_launch(void* const* d_in, const int* in_sizes, int n_in,
                              void* d_out, int out_size) {
    const float* m1      = (const float*)d_in[0];  // modal1_inputs [N, 512]
    const float* m2      = (const float*)d_in[1];  // modal2_inputs [N, 512]
    const float* centers = (const float*)d_in[2];  // centers [C, 512]
    const int*   targets = (const int*)d_in[3];    // targets [N]

    int N = in_sizes[3];
    int C = in_sizes[2] / D;
    float* out = (float*)d_out;
    float inv_nd = 1.0f / ((float)N * (float)D);

    init_kernel<<<1, 512>>>(out, C);
    hist_kernel<<<64, 512>>>(targets, N, C);
    scan_kernel<<<1, MAXC>>>(C);
    fill_kernel<<<64, 512>>>(targets, N);
    dim3 grid(C, 2);
    reduce_kernel<<<grid, D>>>(m1, m2, centers, out, inv_nd);
}